// round 11
// baseline (speedup 1.0000x reference)
#include <cuda_runtime.h>
#include <cuda_bf16.h>

#define BATCH  64
#define NPTS   1024
#define CHUNKS 32
#define JCH    (NPTS / CHUNKS)      // 32 j per block
#define NJP    (JCH / 2)            // 16 j-pairs
#define TPB    256                  // thread t owns shifts t, t+256, t+512, t+768

// Deterministic scratch (no device-side allocation; zero-initialized globals).
__device__ float g_partial[CHUNKS][BATCH][NPTS];  // 8 MB
__device__ float g_min[BATCH];
__device__ int   g_cnt_b[BATCH];
__device__ int   g_cnt_all;

typedef unsigned long long u64;

// ---- packed f32x2 helpers ---------------------------------------------------
__device__ __forceinline__ void upk2(u64 v, float& a, float& b) {
    asm("mov.b64 {%0, %1}, %2;" : "=f"(a), "=f"(b) : "l"(v));   // pair dies -> free
}
__device__ __forceinline__ u64 pk2(float a, float b) {          // fill only
    u64 r; asm("mov.b64 %0, {%1, %2};" : "=l"(r) : "f"(a), "f"(b)); return r;
}
__device__ __forceinline__ u64 addx2(u64 a, u64 b) {
    u64 r; asm("add.rn.f32x2 %0, %1, %2;" : "=l"(r) : "l"(a), "l"(b)); return r;
}
__device__ __forceinline__ u64 mulx2(u64 a, u64 b) {
    u64 r; asm("mul.rn.f32x2 %0, %1, %2;" : "=l"(r) : "l"(a), "l"(b)); return r;
}
__device__ __forceinline__ u64 fmx2(u64 a, u64 b, u64 c) {
    u64 r; asm("fma.rn.f32x2 %0, %1, %2, %3;" : "=l"(r) : "l"(a), "l"(b), "l"(c)); return r;
}
__device__ __forceinline__ float sqrtapx(float x) {
    float r; asm("sqrt.approx.f32 %0, %1;" : "=f"(r) : "f"(x)); return r;
}

// ---------------------------------------------------------------------------
// Single fused kernel. Grid (CHUNKS, BATCH), TPB=256.
// Thread t owns shifts s = t + 256k (k=0..3); alignment parity of the target
// window is parity(t), constant per thread. Negated target x/y coordinates
// stored as adjacent-j pairs in 4 arrays:
//   XE[m]=(-T.x[2m],-T.x[2m+1])  XO[m]=(-T.x[2m+1],-T.x[2m+2])  (YE/YO same)
// Every (shift, j-pair) combination is ONE direct LDS.64 per coordinate —
// zero pack MOVs in the hot loop. Even lanes read XE, odd lanes XO; each
// 16-lane group spans one contiguous 128B window -> conflict-free (2 wf).
// d2 for both j's of the pair computed packed: addx2, addx2, mulx2, fmx2.
// ---------------------------------------------------------------------------
__global__ void __launch_bounds__(TPB, 5)
snake_kernel(const float2* __restrict__ x, const float2* __restrict__ tg,
             float* __restrict__ out)
{
    __shared__ __align__(16) u64 SM[4 * NPTS];   // [XE | XO | YE | YO], 32 KB
    __shared__ u64 XPX[NJP], XPY[NJP];
    __shared__ float redmin[8];
    __shared__ int lastflag;

    const int b     = blockIdx.y;
    const int chunk = blockIdx.x;
    const int j0    = chunk * JCH;
    const int t     = threadIdx.x;

    const float2* __restrict__ tb = tg + b * NPTS;
    const float2* __restrict__ xb = x  + b * NPTS;

    // Fill the 4 pair arrays. Even pair m = points (2m, 2m+1) (mod N);
    // odd pair m = points (2m+1, 2m+2) (mod N).
    #pragma unroll
    for (int m = t; m < NPTS; m += TPB) {        // 4 iterations
        float4 q = ((const float4*)tb)[m & 511];          // points 2m&1023, +1
        float2 r = tb[2 * ((m + 1) & 511)];               // point (2m+2)&1023
        SM[m]            = pk2(-q.x, -q.z);   // XE
        SM[m + NPTS]     = pk2(-q.z, -r.x);   // XO
        SM[m + 2 * NPTS] = pk2(-q.y, -q.w);   // YE
        SM[m + 3 * NPTS] = pk2(-q.w, -r.y);   // YO
    }
    if (t < NJP) {
        float4 q = ((const float4*)(xb + j0))[t];   // (xj.x,xj.y,xj1.x,xj1.y)
        XPX[t] = pk2(q.x, q.z);
        XPY[t] = pk2(q.y, q.w);
    }
    __syncthreads();

    const int p  = t & 1;                        // alignment parity
    const int e0 = j0 + NPTS - t;                // point index at jj=0,k=0
    const int m0 = (e0 - p) >> 1;                // pair index (>= 0)
    const u64* __restrict__ BX = SM + (p ? NPTS : 0) + m0;   // X base; Y = +2*NPTS

    float acc0 = 0.0f, acc1 = 0.0f, acc2 = 0.0f, acc3 = 0.0f;

    #pragma unroll
    for (int jj = 0; jj < NJP; ++jj) {
        u64 xpx = XPX[jj], xpy = XPY[jj];        // broadcast LDS.64

        {   // k = 0  (shift t)
            u64 tx = BX[jj],            ty = BX[2 * NPTS + jj];
            u64 dx = addx2(xpx, tx),    dy = addx2(xpy, ty);
            u64 d2 = fmx2(dy, dy, mulx2(dx, dx));
            float lo, hi; upk2(d2, lo, hi);
            acc0 += sqrtapx(lo); acc0 += sqrtapx(hi);
        }
        {   // k = 1  (shift t+256)
            u64 tx = BX[jj - 128],      ty = BX[2 * NPTS + jj - 128];
            u64 dx = addx2(xpx, tx),    dy = addx2(xpy, ty);
            u64 d2 = fmx2(dy, dy, mulx2(dx, dx));
            float lo, hi; upk2(d2, lo, hi);
            acc1 += sqrtapx(lo); acc1 += sqrtapx(hi);
        }
        {   // k = 2  (shift t+512)
            u64 tx = BX[jj - 256],      ty = BX[2 * NPTS + jj - 256];
            u64 dx = addx2(xpx, tx),    dy = addx2(xpy, ty);
            u64 d2 = fmx2(dy, dy, mulx2(dx, dx));
            float lo, hi; upk2(d2, lo, hi);
            acc2 += sqrtapx(lo); acc2 += sqrtapx(hi);
        }
        {   // k = 3  (shift t+768)
            u64 tx = BX[jj - 384],      ty = BX[2 * NPTS + jj - 384];
            u64 dx = addx2(xpx, tx),    dy = addx2(xpy, ty);
            u64 d2 = fmx2(dy, dy, mulx2(dx, dx));
            float lo, hi; upk2(d2, lo, hi);
            acc3 += sqrtapx(lo); acc3 += sqrtapx(hi);
        }
    }

    g_partial[chunk][b][t]       = acc0;         // coalesced STG.32 x4
    g_partial[chunk][b][t + 256] = acc1;
    g_partial[chunk][b][t + 512] = acc2;
    g_partial[chunk][b][t + 768] = acc3;

    // ---- last block of this batch reduces it --------------------------------
    __threadfence();
    if (t == 0) {
        int old = atomicAdd(&g_cnt_b[b], 1);
        lastflag = (old == CHUNKS - 1);
    }
    __syncthreads();
    if (!lastflag) return;
    __threadfence();
    if (t == 0) g_cnt_b[b] = 0;                  // reset for next replay

    float mn = 3.4e38f;
    #pragma unroll
    for (int k = 0; k < 4; ++k) {
        int s = t + k * TPB;
        float sum = 0.0f;
        #pragma unroll
        for (int c = 0; c < CHUNKS; ++c)
            sum += __ldcg(&g_partial[c][b][s]);
        mn = fminf(mn, sum);
    }
    #pragma unroll
    for (int o = 16; o > 0; o >>= 1)
        mn = fminf(mn, __shfl_xor_sync(0xFFFFFFFFu, mn, o));
    if ((t & 31) == 0) redmin[t >> 5] = mn;
    __syncthreads();

    if (t == 0) {
        float v = redmin[0];
        #pragma unroll
        for (int w = 1; w < 8; ++w) v = fminf(v, redmin[w]);
        g_min[b] = v;
        __threadfence();
        int old = atomicAdd(&g_cnt_all, 1);
        if (old == BATCH - 1) {                  // last batch-reducer
            g_cnt_all = 0;                       // reset for next replay
            float s = 0.0f;
            #pragma unroll
            for (int bb = 0; bb < BATCH; ++bb)
                s += __ldcg(&g_min[bb]);
            out[0] = s * (1.0f / (float)(BATCH * NPTS));
        }
    }
}

// ---------------------------------------------------------------------------
extern "C" void kernel_launch(void* const* d_in, const int* in_sizes, int n_in,
                              void* d_out, int out_size)
{
    const float2* x  = (const float2*)d_in[0];
    const float2* tg = (const float2*)d_in[1];
    float* out = (float*)d_out;

    dim3 grid(CHUNKS, BATCH);
    snake_kernel<<<grid, TPB>>>(x, tg, out);
}